// round 5
// baseline (speedup 1.0000x reference)
#include <cuda_runtime.h>
#include <cstdint>
#include <cstddef>

// ---------------------------------------------------------------------------
// Problem: out[e] = relu(x[src]@W1[:D] + x[tar]@W1[D:] + b1) @ W2 + b2
// Restructure: precompute P[n] = [x[n]@W1a + b1 | x[n]@W1b]  (one GEMM),
// then per-edge gather + relu-dot.
// ---------------------------------------------------------------------------

#define D_DIM      128
#define N_COLS     256          // 2*D
#define N_MAX      100000

// Scratch (no cudaMalloc allowed)
__device__ float g_P[(size_t)N_MAX * N_COLS];   // ~102.4 MB
__device__ float g_Wc[D_DIM * N_COLS];          // rearranged weights [K=128, N=256]
__device__ int   g_idx32;                       // 1 if edge indices are int32

// ---------------------------------------------------------------------------
// f32x2 packed-math helpers (sm_100+): 2 FMAs per instruction on the FMA pipe
// ---------------------------------------------------------------------------
__device__ __forceinline__ unsigned long long pack2(float lo, float hi) {
    unsigned long long r;
    asm("mov.b64 %0, {%1, %2};" : "=l"(r) : "f"(lo), "f"(hi));
    return r;
}
__device__ __forceinline__ void unpack2(unsigned long long v, float& lo, float& hi) {
    asm("mov.b64 {%0, %1}, %2;" : "=f"(lo), "=f"(hi) : "l"(v));
}
__device__ __forceinline__ unsigned long long fma2(unsigned long long a,
                                                   unsigned long long b,
                                                   unsigned long long c) {
    unsigned long long d;
    asm("fma.rn.f32x2 %0, %1, %2, %3;" : "=l"(d) : "l"(a), "l"(b), "l"(c));
    return d;
}

// ---------------------------------------------------------------------------
// Detect index dtype: int32 data read as int64 gives values >= 2^32 unless the
// neighboring index (high word) happens to be 0.  16 samples => unambiguous.
// ---------------------------------------------------------------------------
__global__ void detect_idx_kernel(const long long* __restrict__ pos) {
    if (threadIdx.x == 0) {
        int is32 = 0;
        #pragma unroll
        for (int i = 0; i < 16; ++i) {
            unsigned long long v = (unsigned long long)pos[i];
            if (v > 0xFFFFFFFFull) is32 = 1;
        }
        g_idx32 = is32;
    }
}

// ---------------------------------------------------------------------------
// Rearrange W1 [256,128] row-major -> Wc [128,256]:
//   Wc[k][n] = W1[k][n]          for n < 128   (first-layer "src" half)
//   Wc[k][n] = W1[128+k][n-128]  for n >= 128  ("tar" half)
// ---------------------------------------------------------------------------
__global__ void prep_w_kernel(const float* __restrict__ W1) {
    int i = blockIdx.x * blockDim.x + threadIdx.x;
    if (i < D_DIM * N_COLS) {
        int k = i / N_COLS;
        int n = i % N_COLS;
        g_Wc[i] = (n < D_DIM) ? W1[k * D_DIM + n]
                              : W1[(D_DIM + k) * D_DIM + (n - D_DIM)];
    }
}

// ---------------------------------------------------------------------------
// SGEMM: P[M, 256] = X[M, 128] @ Wc[128, 256]  (+ b1 on first 128 cols)
// BM=128, BN=128, BK=16, 256 threads, 8x8 microtile, f32x2 accumulation.
// grid = (ceil(M/128), 2)
// ---------------------------------------------------------------------------
__global__ __launch_bounds__(256, 2)
void gemm_kernel(const float* __restrict__ X, const float* __restrict__ b1, int M) {
    __shared__ float As[16][128];   // [k][m] (transposed tile of X)
    __shared__ float Bs[16][128];   // [k][n]

    const int tid  = threadIdx.x;
    const int m0   = blockIdx.x * 128;
    const int n0   = blockIdx.y * 128;
    const int tRow = tid >> 4;      // 0..15
    const int tCol = tid & 15;      // 0..15

    unsigned long long acc[8][4];
    #pragma unroll
    for (int i = 0; i < 8; ++i)
        #pragma unroll
        for (int j = 0; j < 4; ++j)
            acc[i][j] = pack2(0.f, 0.f);

    for (int k0 = 0; k0 < D_DIM; k0 += 16) {
        // --- stage X tile [128 rows x 16 cols], transposed into As[k][m]
        #pragma unroll
        for (int l = 0; l < 2; ++l) {
            int idx = tid + l * 256;        // 0..511 float4 slots
            int row = idx >> 2;             // 0..127
            int col = (idx & 3) << 2;       // 0,4,8,12
            int gr  = m0 + row;
            float4 v = make_float4(0.f, 0.f, 0.f, 0.f);
            if (gr < M) v = *(const float4*)(X + (size_t)gr * D_DIM + k0 + col);
            As[col + 0][row] = v.x;
            As[col + 1][row] = v.y;
            As[col + 2][row] = v.z;
            As[col + 3][row] = v.w;
        }
        // --- stage Wc tile [16 rows x 128 cols]
        #pragma unroll
        for (int l = 0; l < 2; ++l) {
            int idx = tid + l * 256;
            int row = idx >> 5;             // 0..15
            int col = (idx & 31) << 2;      // 0..124
            *(float4*)(&Bs[row][col]) =
                *(const float4*)(g_Wc + (size_t)(k0 + row) * N_COLS + n0 + col);
        }
        __syncthreads();

        #pragma unroll
        for (int k = 0; k < 16; ++k) {
            float4 a0 = *(const float4*)(&As[k][tRow * 8]);
            float4 a1 = *(const float4*)(&As[k][tRow * 8 + 4]);
            float4 q0 = *(const float4*)(&Bs[k][tCol * 8]);
            float4 q1 = *(const float4*)(&Bs[k][tCol * 8 + 4]);
            unsigned long long bp[4];
            bp[0] = pack2(q0.x, q0.y);
            bp[1] = pack2(q0.z, q0.w);
            bp[2] = pack2(q1.x, q1.y);
            bp[3] = pack2(q1.z, q1.w);
            float av[8] = {a0.x, a0.y, a0.z, a0.w, a1.x, a1.y, a1.z, a1.w};
            #pragma unroll
            for (int i = 0; i < 8; ++i) {
                unsigned long long ap = pack2(av[i], av[i]);
                #pragma unroll
                for (int j = 0; j < 4; ++j)
                    acc[i][j] = fma2(ap, bp[j], acc[i][j]);
            }
        }
        __syncthreads();
    }

    // --- epilogue: + b1 on the first 128 output cols (blockIdx.y == 0)
    const bool addb = (blockIdx.y == 0);
    float bias[8];
    #pragma unroll
    for (int j = 0; j < 8; ++j)
        bias[j] = addb ? b1[tCol * 8 + j] : 0.f;

    const int nb = n0 + tCol * 8;
    #pragma unroll
    for (int i = 0; i < 8; ++i) {
        int gr = m0 + tRow * 8 + i;
        if (gr < M) {
            float o[8];
            #pragma unroll
            for (int j = 0; j < 4; ++j)
                unpack2(acc[i][j], o[2 * j], o[2 * j + 1]);
            #pragma unroll
            for (int j = 0; j < 8; ++j) o[j] += bias[j];
            float* dst = g_P + (size_t)gr * N_COLS + nb;
            *(float4*)(dst)     = make_float4(o[0], o[1], o[2], o[3]);
            *(float4*)(dst + 4) = make_float4(o[4], o[5], o[6], o[7]);
        }
    }
}

// ---------------------------------------------------------------------------
// Edge kernel: one warp per edge.  Lane l handles 4 features via float4.
// out[e] = sum_d relu(P[src][d] + P[tar][128+d]) * W2[d] + b2
// ---------------------------------------------------------------------------
__global__ __launch_bounds__(256)
void edge_kernel(const long long* __restrict__ pos,
                 const long long* __restrict__ neg,
                 const float* __restrict__ W2,
                 const float* __restrict__ b2,
                 float* __restrict__ out,
                 int Epos, int Eneg) {
    const int warp = (blockIdx.x * blockDim.x + threadIdx.x) >> 5;
    const int lane = threadIdx.x & 31;
    const int Etot = Epos + Eneg;
    if (warp >= Etot) return;

    long long src, tar;
    if (g_idx32) {
        if (warp < Epos) {
            const int* p = (const int*)pos;
            src = p[warp];  tar = p[Epos + warp];
        } else {
            const int* p = (const int*)neg;
            int e = warp - Epos;
            src = p[e];     tar = p[Eneg + e];
        }
    } else {
        if (warp < Epos) {
            src = pos[warp];  tar = pos[Epos + warp];
        } else {
            int e = warp - Epos;
            src = neg[e];     tar = neg[Eneg + e];
        }
    }

    const float4 a = *(const float4*)(g_P + (size_t)src * N_COLS + lane * 4);
    const float4 b = *(const float4*)(g_P + (size_t)tar * N_COLS + D_DIM + lane * 4);
    const float4 w = *(const float4*)(W2 + lane * 4);

    float s = fmaxf(a.x + b.x, 0.f) * w.x
            + fmaxf(a.y + b.y, 0.f) * w.y
            + fmaxf(a.z + b.z, 0.f) * w.z
            + fmaxf(a.w + b.w, 0.f) * w.w;

    #pragma unroll
    for (int off = 16; off; off >>= 1)
        s += __shfl_xor_sync(0xffffffffu, s, off);

    if (lane == 0) out[warp] = s + b2[0];
}

// ---------------------------------------------------------------------------
extern "C" void kernel_launch(void* const* d_in, const int* in_sizes, int n_in,
                              void* d_out, int out_size) {
    const float* x   = (const float*)d_in[0];
    const void*  pos = d_in[1];
    const void*  neg = d_in[2];
    const float* W1  = (const float*)d_in[3];
    const float* b1  = (const float*)d_in[4];
    const float* W2  = (const float*)d_in[5];
    const float* b2  = (const float*)d_in[6];
    float* out = (float*)d_out;

    const int M    = in_sizes[0] / D_DIM;
    const int Epos = in_sizes[1] / 2;
    const int Eneg = in_sizes[2] / 2;
    const int Etot = Epos + Eneg;

    detect_idx_kernel<<<1, 32>>>((const long long*)pos);
    prep_w_kernel<<<(D_DIM * N_COLS + 255) / 256, 256>>>(W1);

    dim3 gg((unsigned)((M + 127) / 128), 2);
    gemm_kernel<<<gg, 256>>>(x, b1, M);

    long long tthreads = (long long)Etot * 32;
    unsigned eblocks = (unsigned)((tthreads + 255) / 256);
    edge_kernel<<<eblocks, 256>>>((const long long*)pos, (const long long*)neg,
                                  W2, b2, out, Epos, Eneg);
}

// round 10
// speedup vs baseline: 1.5933x; 1.5933x over previous
#include <cuda_runtime.h>
#include <cstdint>
#include <cstddef>

// ---------------------------------------------------------------------------
// out[e] = relu(x[src]@W1[:D] + x[tar]@W1[D:] + b1) @ W2 + b2
// Stage 1: P[n] = [x[n]@W1a + b1 | x[n]@W1b]  via mma.sync tf32 (legacy TC path;
//          tcgen05 unavailable: harness PTX target is compute_103 without 'a')
// Stage 2: per-edge gather + relu-dot, 4 edges per warp for MLP.
// ---------------------------------------------------------------------------

#define D_DIM  128
#define N_COLS 256
#define N_MAX  100000

__device__ float g_P[(size_t)N_MAX * N_COLS];   // ~102.4 MB scratch
__device__ float g_Bt[N_COLS * D_DIM];          // B[n][k], tf32-rounded, K-major
__device__ int   g_idx32;

// ------------------------------ helpers ------------------------------------
__device__ __forceinline__ uint32_t smem_u32(const void* p) {
    uint32_t a;
    asm("{ .reg .u64 t; cvta.to.shared.u64 t, %1; cvt.u32.u64 %0, t; }"
        : "=r"(a) : "l"(p));
    return a;
}
__device__ __forceinline__ uint32_t to_tf32(float f) {
    uint32_t r;
    asm("cvt.rna.tf32.f32 %0, %1;" : "=r"(r) : "f"(f));
    return r;
}
__device__ __forceinline__ void ldsm_x4(uint32_t& r0, uint32_t& r1,
                                        uint32_t& r2, uint32_t& r3, uint32_t addr) {
    asm volatile("ldmatrix.sync.aligned.m8n8.x4.shared.b16 {%0,%1,%2,%3}, [%4];"
                 : "=r"(r0), "=r"(r1), "=r"(r2), "=r"(r3) : "r"(addr));
}
__device__ __forceinline__ void mma_tf32(float& c0, float& c1, float& c2, float& c3,
                                         uint32_t a0, uint32_t a1, uint32_t a2, uint32_t a3,
                                         uint32_t b0, uint32_t b1) {
    asm volatile(
        "mma.sync.aligned.m16n8k8.row.col.f32.tf32.tf32.f32 "
        "{%0,%1,%2,%3}, {%4,%5,%6,%7}, {%8,%9}, {%0,%1,%2,%3};"
        : "+f"(c0), "+f"(c1), "+f"(c2), "+f"(c3)
        : "r"(a0), "r"(a1), "r"(a2), "r"(a3), "r"(b0), "r"(b1));
}
__device__ __forceinline__ uint32_t swz(uint32_t byte) {   // SW128: Swizzle<3,4,3>
    return byte ^ ((byte >> 3) & 0x70u);
}

// ---------------------------------------------------------------------------
// index dtype detection (int32 vs int64 on disk)
// ---------------------------------------------------------------------------
__global__ void detect_idx_kernel(const long long* __restrict__ pos) {
    if (threadIdx.x == 0) {
        int is32 = 0;
        #pragma unroll
        for (int i = 0; i < 16; ++i)
            if ((unsigned long long)pos[i] > 0xFFFFFFFFull) is32 = 1;
        g_idx32 = is32;
    }
}

// ---------------------------------------------------------------------------
// Build B[n][k] (tf32-rounded) from W1 [256,128] row-major:
//   n<128:  B[n][k] = W1[k][n]          (src half)
//   n>=128: B[n][k] = W1[128+k][n-128]  (tar half)
// ---------------------------------------------------------------------------
__global__ void prep_w_kernel(const float* __restrict__ W1) {
    int i = blockIdx.x * blockDim.x + threadIdx.x;
    if (i < N_COLS * D_DIM) {
        int n = i / D_DIM, k = i % D_DIM;
        float v = (n < D_DIM) ? W1[k * D_DIM + n]
                              : W1[(D_DIM + k) * D_DIM + (n - D_DIM)];
        g_Bt[i] = __uint_as_float(to_tf32(v));
    }
}

// ---------------------------------------------------------------------------
// tf32 mma.sync GEMM: P[M,256] = X[M,128] @ B^T (+ b1 on cols 0..127)
// BM=128, BN=128, BK=32, 256 threads = 8 warps (4 m-groups x 2 n-groups).
// Warp tile 32x64 = 2 m-atoms x 8 n-atoms of m16n8k8.
// Both A and B staged K-major (rows of 128B) with SW128 swizzle -> ldmatrix.
// grid = (ceil(M/128), 2)
// ---------------------------------------------------------------------------
__global__ __launch_bounds__(256, 2)
void gemm_mma_kernel(const float* __restrict__ X, const float* __restrict__ b1, int M) {
    __shared__ __align__(1024) float sA[128 * 32];   // 16 KB
    __shared__ __align__(1024) float sB[128 * 32];   // 16 KB

    const int tid    = threadIdx.x;
    const int lane   = tid & 31;
    const int wid    = tid >> 5;
    const int warp_m = wid >> 1;        // 0..3 -> 32 m-rows each
    const int warp_n = wid & 1;         // 0..1 -> 64 n-cols each
    const int m0     = blockIdx.x * 128;
    const int nhalf  = blockIdx.y;      // 0: cols 0..127 (+b1), 1: cols 128..255

    const uint32_t sbA = smem_u32(sA);
    const uint32_t sbB = smem_u32(sB);

    float acc[2][8][4];
    #pragma unroll
    for (int i = 0; i < 2; ++i)
        #pragma unroll
        for (int j = 0; j < 8; ++j)
            #pragma unroll
            for (int c = 0; c < 4; ++c) acc[i][j][c] = 0.f;

    // ldmatrix lane->address components (constant across stages)
    //   A x4 tile order: (m0-7,kh0)(m8-15,kh0)(m0-7,kh1)(m8-15,kh1)
    const int a_mrow  = warp_m * 32 + (lane & 15);    // + am*16
    const int a_khalf = lane >> 4;                    // 0/1
    //   B x4 tile order: (n0-7,kh0)(n0-7,kh1)(n8-15,kh0)(n8-15,kh1)
    const int b_nrow  = warp_n * 64 + ((lane >> 4) << 3) + (lane & 7);  // + bn*16
    const int b_khalf = (lane >> 3) & 1;

    for (int k0 = 0; k0 < D_DIM; k0 += 32) {
        // ---- stage A: 128 rows x 8 float4 (tf32-round on the fly)
        #pragma unroll
        for (int i = 0; i < 4; ++i) {
            int idx = tid + i * 256;            // 0..1023
            int row = idx >> 3, c4 = idx & 7;
            int gr  = m0 + row;
            float4 v = make_float4(0.f, 0.f, 0.f, 0.f);
            if (gr < M) v = *(const float4*)(X + (size_t)gr * D_DIM + k0 + c4 * 4);
            uint4 t;
            t.x = to_tf32(v.x); t.y = to_tf32(v.y); t.z = to_tf32(v.z); t.w = to_tf32(v.w);
            *(uint4*)((char*)sA + swz((row << 7) + (c4 << 4))) = t;
        }
        // ---- stage B: rows nhalf*128 .. +127 of g_Bt (already tf32-rounded)
        #pragma unroll
        for (int i = 0; i < 4; ++i) {
            int idx = tid + i * 256;
            int row = idx >> 3, c4 = idx & 7;
            float4 v = *(const float4*)(g_Bt + (size_t)(nhalf * 128 + row) * D_DIM + k0 + c4 * 4);
            *(float4*)((char*)sB + swz((row << 7) + (c4 << 4))) = v;
        }
        __syncthreads();

        #pragma unroll
        for (int ks = 0; ks < 4; ++ks) {        // k8-steps within BK=32
            uint32_t a[2][4], b[4][4];
            #pragma unroll
            for (int am = 0; am < 2; ++am) {
                uint32_t byte = ((a_mrow + am * 16) << 7) + ((ks * 2 + a_khalf) << 4);
                ldsm_x4(a[am][0], a[am][1], a[am][2], a[am][3], sbA + swz(byte));
            }
            #pragma unroll
            for (int bn = 0; bn < 4; ++bn) {
                uint32_t byte = ((b_nrow + bn * 16) << 7) + ((ks * 2 + b_khalf) << 4);
                ldsm_x4(b[bn][0], b[bn][1], b[bn][2], b[bn][3], sbB + swz(byte));
            }
            #pragma unroll
            for (int am = 0; am < 2; ++am)
                #pragma unroll
                for (int na = 0; na < 8; ++na) {
                    uint32_t b0 = b[na >> 1][(na & 1) * 2];
                    uint32_t b1r = b[na >> 1][(na & 1) * 2 + 1];
                    mma_tf32(acc[am][na][0], acc[am][na][1], acc[am][na][2], acc[am][na][3],
                             a[am][0], a[am][1], a[am][2], a[am][3], b0, b1r);
                }
        }
        __syncthreads();
    }

    // ---- epilogue: direct float2 stores (c-frag layout), + b1 on half 0
    const int g  = lane >> 2;
    const int tq = lane & 3;
    float2 bias[8];
    #pragma unroll
    for (int na = 0; na < 8; ++na) {
        if (nhalf == 0) {
            bias[na] = *(const float2*)(b1 + warp_n * 64 + na * 8 + tq * 2);
        } else {
            bias[na] = make_float2(0.f, 0.f);
        }
    }
    #pragma unroll
    for (int am = 0; am < 2; ++am) {
        int r0 = m0 + warp_m * 32 + am * 16 + g;
        int r1 = r0 + 8;
        #pragma unroll
        for (int na = 0; na < 8; ++na) {
            int col = nhalf * 128 + warp_n * 64 + na * 8 + tq * 2;
            if (r0 < M)
                *(float2*)(g_P + (size_t)r0 * N_COLS + col) =
                    make_float2(acc[am][na][0] + bias[na].x, acc[am][na][1] + bias[na].y);
            if (r1 < M)
                *(float2*)(g_P + (size_t)r1 * N_COLS + col) =
                    make_float2(acc[am][na][2] + bias[na].x, acc[am][na][3] + bias[na].y);
        }
    }
}

// ---------------------------------------------------------------------------
// Edge kernel: 4 edges per warp (MLP=8 on the gathered rows).
// out[e] = sum_d relu(P[src][d] + P[tar][128+d]) * W2[d] + b2
// ---------------------------------------------------------------------------
__global__ __launch_bounds__(256)
void edge_kernel(const long long* __restrict__ pos,
                 const long long* __restrict__ neg,
                 const float* __restrict__ W2,
                 const float* __restrict__ b2,
                 float* __restrict__ out,
                 int Epos, int Eneg) {
    const int warp = (blockIdx.x * blockDim.x + threadIdx.x) >> 5;
    const int lane = threadIdx.x & 31;
    const int Etot = Epos + Eneg;
    const int e0   = warp * 4;
    if (e0 >= Etot) return;

    const int idx32 = g_idx32;

    long long sidx[4], tidx[4];
    #pragma unroll
    for (int j = 0; j < 4; ++j) {
        int e = e0 + j;
        if (e >= Etot) { sidx[j] = 0; tidx[j] = 0; continue; }
        if (idx32) {
            if (e < Epos) {
                const int* p = (const int*)pos;
                sidx[j] = p[e];          tidx[j] = p[Epos + e];
            } else {
                const int* p = (const int*)neg;
                int q = e - Epos;
                sidx[j] = p[q];          tidx[j] = p[Eneg + q];
            }
        } else {
            if (e < Epos) { sidx[j] = pos[e];        tidx[j] = pos[Epos + e]; }
            else          { int q = e - Epos;
                            sidx[j] = neg[q];        tidx[j] = neg[Eneg + q]; }
        }
    }

    const float4 w = *(const float4*)(W2 + lane * 4);

    float4 av[4], bv[4];
    #pragma unroll
    for (int j = 0; j < 4; ++j) {
        av[j] = *(const float4*)(g_P + (size_t)sidx[j] * N_COLS + lane * 4);
        bv[j] = *(const float4*)(g_P + (size_t)tidx[j] * N_COLS + D_DIM + lane * 4);
    }

    float s[4];
    #pragma unroll
    for (int j = 0; j < 4; ++j) {
        s[j] = fmaxf(av[j].x + bv[j].x, 0.f) * w.x
             + fmaxf(av[j].y + bv[j].y, 0.f) * w.y
             + fmaxf(av[j].z + bv[j].z, 0.f) * w.z
             + fmaxf(av[j].w + bv[j].w, 0.f) * w.w;
    }

    #pragma unroll
    for (int off = 16; off; off >>= 1) {
        #pragma unroll
        for (int j = 0; j < 4; ++j)
            s[j] += __shfl_xor_sync(0xffffffffu, s[j], off);
    }

    if (lane == 0) {
        const float bb = b2[0];
        #pragma unroll
        for (int j = 0; j < 4; ++j)
            if (e0 + j < Etot) out[e0 + j] = s[j] + bb;
    }
}

// ---------------------------------------------------------------------------
extern "C" void kernel_launch(void* const* d_in, const int* in_sizes, int n_in,
                              void* d_out, int out_size) {
    const float* x   = (const float*)d_in[0];
    const void*  pos = d_in[1];
    const void*  neg = d_in[2];
    const float* W1  = (const float*)d_in[3];
    const float* b1  = (const float*)d_in[4];
    const float* W2  = (const float*)d_in[5];
    const float* b2  = (const float*)d_in[6];
    float* out = (float*)d_out;

    const int M    = in_sizes[0] / D_DIM;
    const int Epos = in_sizes[1] / 2;
    const int Eneg = in_sizes[2] / 2;
    const int Etot = Epos + Eneg;
    const int ntiles = (M + 127) / 128;

    detect_idx_kernel<<<1, 32>>>((const long long*)pos);
    prep_w_kernel<<<(N_COLS * D_DIM + 255) / 256, 256>>>(W1);

    dim3 gg((unsigned)ntiles, 2);
    gemm_mma_kernel<<<gg, 256>>>(x, b1, M);

    int warps = (Etot + 3) / 4;
    unsigned eblocks = (unsigned)((warps + 7) / 8);     // 8 warps / 256-thr block
    edge_kernel<<<eblocks, 256>>>((const long long*)pos, (const long long*)neg,
                                  W2, b2, out, Epos, Eneg);
}

// round 11
// speedup vs baseline: 2.1789x; 1.3675x over previous
#include <cuda_runtime.h>
#include <cstdint>
#include <cstddef>

// ---------------------------------------------------------------------------
// out[e] = relu(x[src]@W1[:D] + x[tar]@W1[D:] + b1) @ W2 + b2
// Stage 1: P[n] = [x[n]@W1a + b1 | x[n]@W1b]  via mma.sync tf32 + cp.async
//          double-buffered pipeline (tcgen05 unavailable: PTX target compute_103)
// Stage 2: per-edge gather + relu-dot, 4 edges per warp.
// ---------------------------------------------------------------------------

#define D_DIM  128
#define N_COLS 256
#define N_MAX  100000

__device__ float g_P[(size_t)N_MAX * N_COLS];   // ~102.4 MB scratch
__device__ float g_Bt[N_COLS * D_DIM];          // B[n][k], tf32-rounded, K-major
__device__ int   g_idx32;

// ------------------------------ helpers ------------------------------------
__device__ __forceinline__ uint32_t smem_u32(const void* p) {
    uint32_t a;
    asm("{ .reg .u64 t; cvta.to.shared.u64 t, %1; cvt.u32.u64 %0, t; }"
        : "=r"(a) : "l"(p));
    return a;
}
__device__ __forceinline__ uint32_t to_tf32(float f) {
    uint32_t r;
    asm("cvt.rna.tf32.f32 %0, %1;" : "=r"(r) : "f"(f));
    return r;
}
__device__ __forceinline__ void ldsm_x4(uint32_t& r0, uint32_t& r1,
                                        uint32_t& r2, uint32_t& r3, uint32_t addr) {
    asm volatile("ldmatrix.sync.aligned.m8n8.x4.shared.b16 {%0,%1,%2,%3}, [%4];"
                 : "=r"(r0), "=r"(r1), "=r"(r2), "=r"(r3) : "r"(addr));
}
__device__ __forceinline__ void mma_tf32(float& c0, float& c1, float& c2, float& c3,
                                         uint32_t a0, uint32_t a1, uint32_t a2, uint32_t a3,
                                         uint32_t b0, uint32_t b1) {
    asm volatile(
        "mma.sync.aligned.m16n8k8.row.col.f32.tf32.tf32.f32 "
        "{%0,%1,%2,%3}, {%4,%5,%6,%7}, {%8,%9}, {%0,%1,%2,%3};"
        : "+f"(c0), "+f"(c1), "+f"(c2), "+f"(c3)
        : "r"(a0), "r"(a1), "r"(a2), "r"(a3), "r"(b0), "r"(b1));
}
__device__ __forceinline__ uint32_t swz(uint32_t byte) {   // SW128: Swizzle<3,4,3>
    return byte ^ ((byte >> 3) & 0x70u);
}
// cp.async 16B with zero-fill when nbytes==0
__device__ __forceinline__ void cp16(uint32_t dst, const void* src, int nbytes) {
    asm volatile("cp.async.cg.shared.global [%0], [%1], 16, %2;"
                 :: "r"(dst), "l"(__cvta_generic_to_global(src)), "r"(nbytes));
}
#define CP_COMMIT() asm volatile("cp.async.commit_group;" ::: "memory")
#define CP_WAIT0()  asm volatile("cp.async.wait_group 0;" ::: "memory")

// ---------------------------------------------------------------------------
// index dtype detection (int32 vs int64 on disk)
// ---------------------------------------------------------------------------
__global__ void detect_idx_kernel(const long long* __restrict__ pos) {
    if (threadIdx.x == 0) {
        int is32 = 0;
        #pragma unroll
        for (int i = 0; i < 16; ++i)
            if ((unsigned long long)pos[i] > 0xFFFFFFFFull) is32 = 1;
        g_idx32 = is32;
    }
}

// ---------------------------------------------------------------------------
// Build B[n][k] (tf32-rounded) from W1 [256,128] row-major:
//   n<128:  B[n][k] = W1[k][n]          (src half)
//   n>=128: B[n][k] = W1[128+k][n-128]  (tar half)
// ---------------------------------------------------------------------------
__global__ void prep_w_kernel(const float* __restrict__ W1) {
    int i = blockIdx.x * blockDim.x + threadIdx.x;
    if (i < N_COLS * D_DIM) {
        int n = i / D_DIM, k = i % D_DIM;
        float v = (n < D_DIM) ? W1[k * D_DIM + n]
                              : W1[(D_DIM + k) * D_DIM + (n - D_DIM)];
        g_Bt[i] = __uint_as_float(to_tf32(v));
    }
}

// ---------------------------------------------------------------------------
// tf32 mma.sync GEMM, cp.async double-buffered:
// P[M,256] = X[M,128] @ B^T (+ b1 on cols 0..127)
// BM=128, BN=128, BK=32 (4 stages), 256 threads = 8 warps (4m x 2n).
// Warp tile 32x64 = 2 m-atoms x 8 n-atoms of m16n8k8.
// A copied raw fp32 (cvt.rna applied on ldmatrix fragments); B pre-rounded.
// smem: A[2] 16KB + B[2] 16KB = 64KB dynamic (+1KB align pad), 2 CTAs/SM.
// grid = (ceil(M/128), 2)
// ---------------------------------------------------------------------------
#define SA_OFF(b) ((b) * 16384)
#define SB_OFF(b) (32768 + (b) * 16384)
#define GEMM_SMEM (65536 + 1024)

__global__ __launch_bounds__(256, 2)
void gemm_mma_kernel(const float* __restrict__ X, const float* __restrict__ b1, int M) {
    extern __shared__ char smem_raw[];
    const uint32_t sb = (smem_u32(smem_raw) + 1023u) & ~1023u;   // 1KB-align

    const int tid    = threadIdx.x;
    const int lane   = tid & 31;
    const int wid    = tid >> 5;
    const int warp_m = wid >> 1;        // 0..3 -> 32 m-rows each
    const int warp_n = wid & 1;         // 0..1 -> 64 n-cols each
    const int m0     = blockIdx.x * 128;
    const int nhalf  = blockIdx.y;      // 0: cols 0..127 (+b1), 1: cols 128..255

    float acc[2][8][4];
    #pragma unroll
    for (int i = 0; i < 2; ++i)
        #pragma unroll
        for (int j = 0; j < 8; ++j)
            #pragma unroll
            for (int c = 0; c < 4; ++c) acc[i][j][c] = 0.f;

    // staging thread->element map: 1024 16B cells per tile, 4 per thread
    const int st_row0 = tid >> 3;       // 0..31 (+32 per i)
    const int st_c4   = tid & 7;

    // ldmatrix lane->address components
    const int a_mrow  = warp_m * 32 + (lane & 15);
    const int a_khalf = lane >> 4;
    const int b_nrow  = warp_n * 64 + ((lane >> 4) << 3) + (lane & 7);
    const int b_khalf = (lane >> 3) & 1;

#define STAGE(k0, bsel) do {                                                   \
    _Pragma("unroll")                                                          \
    for (int i = 0; i < 4; ++i) {                                              \
        int row = st_row0 + i * 32;                                            \
        uint32_t off = swz((uint32_t)(row << 7) + (uint32_t)(st_c4 << 4));     \
        int gr = m0 + row;                                                     \
        const float* srcA = X + (size_t)(gr < M ? gr : 0) * D_DIM + (k0) + st_c4 * 4; \
        cp16(sb + SA_OFF(bsel) + off, srcA, gr < M ? 16 : 0);                  \
        const float* srcB = g_Bt + (size_t)(nhalf * 128 + row) * D_DIM + (k0) + st_c4 * 4; \
        cp16(sb + SB_OFF(bsel) + off, srcB, 16);                               \
    }                                                                          \
    CP_COMMIT();                                                               \
} while (0)

    STAGE(0, 0);
    int buf = 0;

    #pragma unroll
    for (int s = 0; s < 4; ++s) {
        CP_WAIT0();
        __syncthreads();
        if (s < 3) STAGE((s + 1) * 32, buf ^ 1);

        const uint32_t bA = sb + SA_OFF(buf);
        const uint32_t bB = sb + SB_OFF(buf);

        #pragma unroll
        for (int ks = 0; ks < 4; ++ks) {
            uint32_t a[2][4], b[4][4];
            #pragma unroll
            for (int am = 0; am < 2; ++am) {
                uint32_t byte = ((uint32_t)(a_mrow + am * 16) << 7)
                              + ((uint32_t)(ks * 2 + a_khalf) << 4);
                ldsm_x4(a[am][0], a[am][1], a[am][2], a[am][3], bA + swz(byte));
                #pragma unroll
                for (int j = 0; j < 4; ++j)
                    a[am][j] = to_tf32(__uint_as_float(a[am][j]));
            }
            #pragma unroll
            for (int bn = 0; bn < 4; ++bn) {
                uint32_t byte = ((uint32_t)(b_nrow + bn * 16) << 7)
                              + ((uint32_t)(ks * 2 + b_khalf) << 4);
                ldsm_x4(b[bn][0], b[bn][1], b[bn][2], b[bn][3], bB + swz(byte));
            }
            #pragma unroll
            for (int am = 0; am < 2; ++am)
                #pragma unroll
                for (int na = 0; na < 8; ++na) {
                    uint32_t b0  = b[na >> 1][(na & 1) * 2];
                    uint32_t b1r = b[na >> 1][(na & 1) * 2 + 1];
                    mma_tf32(acc[am][na][0], acc[am][na][1], acc[am][na][2], acc[am][na][3],
                             a[am][0], a[am][1], a[am][2], a[am][3], b0, b1r);
                }
        }
        __syncthreads();
        buf ^= 1;
    }
#undef STAGE

    // ---- epilogue: direct float2 stores (c-frag layout), + b1 on half 0
    const int g  = lane >> 2;
    const int tq = lane & 3;
    float2 bias[8];
    #pragma unroll
    for (int na = 0; na < 8; ++na) {
        if (nhalf == 0) {
            bias[na] = *(const float2*)(b1 + warp_n * 64 + na * 8 + tq * 2);
        } else {
            bias[na] = make_float2(0.f, 0.f);
        }
    }
    #pragma unroll
    for (int am = 0; am < 2; ++am) {
        int r0 = m0 + warp_m * 32 + am * 16 + g;
        int r1 = r0 + 8;
        #pragma unroll
        for (int na = 0; na < 8; ++na) {
            int col = nhalf * 128 + warp_n * 64 + na * 8 + tq * 2;
            if (r0 < M)
                *(float2*)(g_P + (size_t)r0 * N_COLS + col) =
                    make_float2(acc[am][na][0] + bias[na].x, acc[am][na][1] + bias[na].y);
            if (r1 < M)
                *(float2*)(g_P + (size_t)r1 * N_COLS + col) =
                    make_float2(acc[am][na][2] + bias[na].x, acc[am][na][3] + bias[na].y);
        }
    }
}

// ---------------------------------------------------------------------------
// Edge kernel: 4 edges per warp (unchanged — near the L2 gather roofline)
// out[e] = sum_d relu(P[src][d] + P[tar][128+d]) * W2[d] + b2
// ---------------------------------------------------------------------------
__global__ __launch_bounds__(256)
void edge_kernel(const long long* __restrict__ pos,
                 const long long* __restrict__ neg,
                 const float* __restrict__ W2,
                 const float* __restrict__ b2,
                 float* __restrict__ out,
                 int Epos, int Eneg) {
    const int warp = (blockIdx.x * blockDim.x + threadIdx.x) >> 5;
    const int lane = threadIdx.x & 31;
    const int Etot = Epos + Eneg;
    const int e0   = warp * 4;
    if (e0 >= Etot) return;

    const int idx32 = g_idx32;

    long long sidx[4], tidx[4];
    #pragma unroll
    for (int j = 0; j < 4; ++j) {
        int e = e0 + j;
        if (e >= Etot) { sidx[j] = 0; tidx[j] = 0; continue; }
        if (idx32) {
            if (e < Epos) {
                const int* p = (const int*)pos;
                sidx[j] = p[e];          tidx[j] = p[Epos + e];
            } else {
                const int* p = (const int*)neg;
                int q = e - Epos;
                sidx[j] = p[q];          tidx[j] = p[Eneg + q];
            }
        } else {
            if (e < Epos) { sidx[j] = pos[e];        tidx[j] = pos[Epos + e]; }
            else          { int q = e - Epos;
                            sidx[j] = neg[q];        tidx[j] = neg[Eneg + q]; }
        }
    }

    const float4 w = *(const float4*)(W2 + lane * 4);

    float4 av[4], bv[4];
    #pragma unroll
    for (int j = 0; j < 4; ++j) {
        av[j] = *(const float4*)(g_P + (size_t)sidx[j] * N_COLS + lane * 4);
        bv[j] = *(const float4*)(g_P + (size_t)tidx[j] * N_COLS + D_DIM + lane * 4);
    }

    float s[4];
    #pragma unroll
    for (int j = 0; j < 4; ++j) {
        s[j] = fmaxf(av[j].x + bv[j].x, 0.f) * w.x
             + fmaxf(av[j].y + bv[j].y, 0.f) * w.y
             + fmaxf(av[j].z + bv[j].z, 0.f) * w.z
             + fmaxf(av[j].w + bv[j].w, 0.f) * w.w;
    }

    #pragma unroll
    for (int off = 16; off; off >>= 1) {
        #pragma unroll
        for (int j = 0; j < 4; ++j)
            s[j] += __shfl_xor_sync(0xffffffffu, s[j], off);
    }

    if (lane == 0) {
        const float bb = b2[0];
        #pragma unroll
        for (int j = 0; j < 4; ++j)
            if (e0 + j < Etot) out[e0 + j] = s[j] + bb;
    }
}

// ---------------------------------------------------------------------------
extern "C" void kernel_launch(void* const* d_in, const int* in_sizes, int n_in,
                              void* d_out, int out_size) {
    const float* x   = (const float*)d_in[0];
    const void*  pos = d_in[1];
    const void*  neg = d_in[2];
    const float* W1  = (const float*)d_in[3];
    const float* b1  = (const float*)d_in[4];
    const float* W2  = (const float*)d_in[5];
    const float* b2  = (const float*)d_in[6];
    float* out = (float*)d_out;

    const int M    = in_sizes[0] / D_DIM;
    const int Epos = in_sizes[1] / 2;
    const int Eneg = in_sizes[2] / 2;
    const int Etot = Epos + Eneg;
    const int ntiles = (M + 127) / 128;

    static bool attr_set = false;
    if (!attr_set) {
        cudaFuncSetAttribute(gemm_mma_kernel,
                             cudaFuncAttributeMaxDynamicSharedMemorySize, GEMM_SMEM);
        attr_set = true;
    }

    detect_idx_kernel<<<1, 32>>>((const long long*)pos);
    prep_w_kernel<<<(N_COLS * D_DIM + 255) / 256, 256>>>(W1);

    dim3 gg((unsigned)ntiles, 2);
    gemm_mma_kernel<<<gg, 256, GEMM_SMEM>>>(x, b1, M);

    int warps = (Etot + 3) / 4;
    unsigned eblocks = (unsigned)((warps + 7) / 8);     // 8 warps / 256-thr block
    edge_kernel<<<eblocks, 256>>>((const long long*)pos, (const long long*)neg,
                                  W2, b2, out, Epos, Eneg);
}